// round 7
// baseline (speedup 1.0000x reference)
#include <cuda_runtime.h>
#include <cuda_bf16.h>
#include <math.h>

#define N_NODES 100000
#define N_EDGES 1600000
#define D 64
#define EPSV 1e-7f
#define SCAN_BLK 1024
#define N_SCAN_BLKS ((N_NODES + SCAN_BLK - 1) / SCAN_BLK)   // 98

#define FIN_NODES 96
#define FIN_SMEM (FIN_NODES * 448 * 4)   // 172032 B

// Scratch (device globals; allocation is forbidden)
__device__ float g_s1[N_NODES * D];
__device__ float g_s2[N_NODES * D];
__device__ int   g_cnt[N_NODES];
__device__ int   g_rowptr[N_NODES + 1];
__device__ int   g_cur[N_NODES];
__device__ int   g_bsum[N_SCAN_BLKS];
__device__ int   g_csr[N_EDGES];
__device__ float g_wt[448 * 64];     // permuted weights (k-pair interleaved)

// ---------------------------------------------------------------------------
// K0: permute weights (lane-coalesced k-pair interleave) + zero g_cnt.
//   kk = k>>1, klo = k&1, og = o>>2, r = o&3
//   didx = kk*128 + (r>>1)*64 + og*4 + (r&1)*2 + klo
// ---------------------------------------------------------------------------
__global__ void permute_zero_kernel(const float* __restrict__ pre_w,
                                    const float* __restrict__ lin_w, int N) {
    int idx = blockIdx.x * blockDim.x + threadIdx.x;
    if (idx < 448 * 64) {
        int k = idx >> 6;
        int o = idx & 63;
        int seg = k >> 6;
        int ki = k & 63;
        const float* W = (seg < 6) ? (pre_w + seg * 4096) : lin_w;
        float v = W[o * 64 + ki];
        int kk = k >> 1, klo = k & 1;
        int og = o >> 2, r = o & 3;
        int didx = kk * 128 + (r >> 1) * 64 + og * 4 + (r & 1) * 2 + klo;
        g_wt[didx] = v;
    }
    if (idx < N) g_cnt[idx] = 0;
}

// ---------------------------------------------------------------------------
// K1: histogram of destination degrees
// ---------------------------------------------------------------------------
__global__ void count_kernel(const int* __restrict__ erow, int E) {
    int e = blockIdx.x * blockDim.x + threadIdx.x;
    if (e < E) atomicAdd(&g_cnt[erow[e]], 1);
}

// ---------------------------------------------------------------------------
// K2a: per-block exclusive scan of g_cnt -> g_rowptr; block totals -> g_bsum
// ---------------------------------------------------------------------------
__global__ void scan_block_kernel(int n) {
    __shared__ int warp_sums[32];
    int i = blockIdx.x * SCAN_BLK + threadIdx.x;
    int v = (i < n) ? g_cnt[i] : 0;
    int lane = threadIdx.x & 31;
    int wid = threadIdx.x >> 5;

    int s = v;
    #pragma unroll
    for (int o = 1; o < 32; o <<= 1) {
        int t = __shfl_up_sync(0xffffffffu, s, o);
        if (lane >= o) s += t;
    }
    if (lane == 31) warp_sums[wid] = s;
    __syncthreads();
    if (wid == 0) {
        int ws = warp_sums[lane];
        #pragma unroll
        for (int o = 1; o < 32; o <<= 1) {
            int t = __shfl_up_sync(0xffffffffu, ws, o);
            if (lane >= o) ws += t;
        }
        warp_sums[lane] = ws;
    }
    __syncthreads();
    int warp_off = (wid == 0) ? 0 : warp_sums[wid - 1];
    if (i < n) g_rowptr[i] = warp_off + s - v;
    if (threadIdx.x == SCAN_BLK - 1) g_bsum[blockIdx.x] = warp_off + s;
}

// ---------------------------------------------------------------------------
// K2b: parallel exclusive scan of the 98 block sums
// ---------------------------------------------------------------------------
__global__ void scan_top_kernel(int nb) {
    __shared__ int sh[128];
    int t = threadIdx.x;
    int v = (t < nb) ? g_bsum[t] : 0;
    int lane = t & 31, wid = t >> 5;
    int s = v;
    #pragma unroll
    for (int o = 1; o < 32; o <<= 1) {
        int u = __shfl_up_sync(0xffffffffu, s, o);
        if (lane >= o) s += u;
    }
    if (lane == 31) sh[wid] = s;
    __syncthreads();
    if (t == 0) {
        int acc = 0;
        #pragma unroll
        for (int w = 0; w < 4; ++w) { int x = sh[w]; sh[w] = acc; acc += x; }
    }
    __syncthreads();
    if (t < nb) g_bsum[t] = sh[wid] + s - v;
}

// ---------------------------------------------------------------------------
// K2c: add block offsets; init cursors; rowptr[N] = E
// ---------------------------------------------------------------------------
__global__ void scan_add_kernel(int n, int E) {
    int i = blockIdx.x * blockDim.x + threadIdx.x;
    if (i < n) {
        int r = g_rowptr[i] + g_bsum[i >> 10];
        g_rowptr[i] = r;
        g_cur[i] = r;
    }
    if (i == n) g_rowptr[n] = E;
}

// ---------------------------------------------------------------------------
// K3: bucket-scatter edge sources into CSR
// ---------------------------------------------------------------------------
__global__ void scatter_kernel(const int* __restrict__ erow,
                               const int* __restrict__ ecol, int E) {
    int e = blockIdx.x * blockDim.x + threadIdx.x;
    if (e < E) {
        int d = erow[e];
        int pos = atomicAdd(&g_cur[d], 1);
        g_csr[pos] = ecol[e];
    }
}

// ---------------------------------------------------------------------------
// K4: gather-aggregate, 16 lanes/node, unrolled by 2 for MLP.
// ---------------------------------------------------------------------------
__global__ void aggregate_kernel(const float* __restrict__ x, int N) {
    int gid = blockIdx.x * blockDim.x + threadIdx.x;
    int n = gid >> 4;
    if (n >= N) return;
    int lane = gid & 15;

    int beg = g_rowptr[n];
    int end = g_rowptr[n + 1];

    float4 a = make_float4(0.f, 0.f, 0.f, 0.f);
    float4 b = make_float4(0.f, 0.f, 0.f, 0.f);
    const float4* x4 = reinterpret_cast<const float4*>(x);

    int j = beg;
    for (; j + 1 < end; j += 2) {
        int s0 = __ldg(&g_csr[j]);
        int s1 = __ldg(&g_csr[j + 1]);
        float4 v0 = __ldg(&x4[(size_t)s0 * 16 + lane]);
        float4 v1 = __ldg(&x4[(size_t)s1 * 16 + lane]);
        a.x += v0.x; a.y += v0.y; a.z += v0.z; a.w += v0.w;
        b.x += v0.x * v0.x; b.y += v0.y * v0.y;
        b.z += v0.z * v0.z; b.w += v0.w * v0.w;
        a.x += v1.x; a.y += v1.y; a.z += v1.z; a.w += v1.w;
        b.x += v1.x * v1.x; b.y += v1.y * v1.y;
        b.z += v1.z * v1.z; b.w += v1.w * v1.w;
    }
    if (j < end) {
        int s0 = __ldg(&g_csr[j]);
        float4 v0 = __ldg(&x4[(size_t)s0 * 16 + lane]);
        a.x += v0.x; a.y += v0.y; a.z += v0.z; a.w += v0.w;
        b.x += v0.x * v0.x; b.y += v0.y * v0.y;
        b.z += v0.z * v0.z; b.w += v0.w * v0.w;
    }

    size_t off = (size_t)n * 16 + lane;
    reinterpret_cast<float4*>(g_s1)[off] = a;
    reinterpret_cast<float4*>(g_s2)[off] = b;
}

// ---------------------------------------------------------------------------
// K5: finalize GEMM, FFMA2 packed along k.
// 96 nodes/CTA (172 KB smem), 256 threads:
//   og = tid&15 -> 4 outputs; ng = tid>>4 -> 6 nodes.
// Per kk: 2 weight LDG.128 serve 24 FFMA2 -> weight wavefronts fully hidden
// under the FMA pipe (48 cyc FMA vs 4 wf per warp).
// ---------------------------------------------------------------------------
__device__ __forceinline__ unsigned long long ffma2(
    unsigned long long a, unsigned long long b, unsigned long long c) {
    unsigned long long d;
    asm("fma.rn.f32x2 %0, %1, %2, %3;" : "=l"(d) : "l"(a), "l"(b), "l"(c));
    return d;
}

__global__ void __launch_bounds__(256, 1)
finalize_kernel(const float* __restrict__ x,
                const float* __restrict__ bias,
                const float* __restrict__ avg_ptr,
                float* __restrict__ out,
                int N) {
    extern __shared__ float Ysh[];                 // [96][448]
    __shared__ float f1s[FIN_NODES], f2s[FIN_NODES];
    const int tid = threadIdx.x;
    const int node0 = blockIdx.x * FIN_NODES;

    if (tid < FIN_NODES) {
        int n = node0 + tid;
        float f1 = 0.f, f2 = 0.f;
        if (n < N) {
            float avg = __ldg(avg_ptr);
            float degf = (float)(g_rowptr[n + 1] - g_rowptr[n]);
            float logd = __logf(degf + 1.0f);
            f1 = logd / avg;
            f2 = avg / (logd + EPSV);
        }
        f1s[tid] = f1;
        f2s[tid] = f2;
    }
    __syncthreads();

    // stage augmented features: 96 nodes x 64 dims = 6144 elements
    #pragma unroll
    for (int t = 0; t < 24; ++t) {
        int p = tid + t * 256;
        int nl = p >> 6;
        int i = p & 63;
        int n = node0 + nl;
        float mean = 0.f, stdv = 0.f, xv = 0.f;
        if (n < N) {
            mean = g_s1[(size_t)n * D + i];
            float s2v = g_s2[(size_t)n * D + i];
            float v = fmaxf(s2v - mean * mean, 0.f) + EPSV;
            stdv = v * rsqrtf(v);            // sqrt(v): 1 MUFU + 1 FMUL
            xv = __ldg(x + (size_t)n * D + i);
        }
        float f1 = f1s[nl], f2 = f2s[nl];
        float* Yr = Ysh + nl * 448;
        Yr[i]       = mean;
        Yr[64 + i]  = f1 * mean;
        Yr[128 + i] = f2 * mean;
        Yr[192 + i] = stdv;
        Yr[256 + i] = f1 * stdv;
        Yr[320 + i] = f2 * stdv;
        Yr[384 + i] = xv;
    }
    __syncthreads();

    const int og = tid & 15;          // outs o0..o0+3
    const int ng = tid >> 4;          // nodes na..na+5
    const int o0 = og * 4;
    const int na = ng * 6;

    unsigned long long acc[6][4];
    #pragma unroll
    for (int j = 0; j < 6; ++j)
        #pragma unroll
        for (int q = 0; q < 4; ++q) acc[j][q] = 0ull;

    const ulonglong2* wbase = reinterpret_cast<const ulonglong2*>(g_wt);
    const unsigned long long* Yp[6];
    #pragma unroll
    for (int j = 0; j < 6; ++j)
        Yp[j] = reinterpret_cast<const unsigned long long*>(
            Ysh + (na + j) * 448);

    #pragma unroll 2
    for (int kk = 0; kk < 224; ++kk) {
        ulonglong2 wlo = __ldg(wbase + kk * 32 + og);         // pairs o0, o0+1
        ulonglong2 whi = __ldg(wbase + kk * 32 + 16 + og);    // pairs o0+2, o0+3
        #pragma unroll
        for (int j = 0; j < 6; ++j) {
            unsigned long long y = Yp[j][kk];
            acc[j][0] = ffma2(y, wlo.x, acc[j][0]);
            acc[j][1] = ffma2(y, wlo.y, acc[j][1]);
            acc[j][2] = ffma2(y, whi.x, acc[j][2]);
            acc[j][3] = ffma2(y, whi.y, acc[j][3]);
        }
    }

    float bz[4];
    #pragma unroll
    for (int q = 0; q < 4; ++q) bz[q] = __ldg(bias + o0 + q);

    #pragma unroll
    for (int j = 0; j < 6; ++j) {
        int n = node0 + na + j;
        if (n < N) {
            float4 r;
            float2 p0 = *reinterpret_cast<float2*>(&acc[j][0]);
            float2 p1 = *reinterpret_cast<float2*>(&acc[j][1]);
            float2 p2 = *reinterpret_cast<float2*>(&acc[j][2]);
            float2 p3 = *reinterpret_cast<float2*>(&acc[j][3]);
            r.x = p0.x + p0.y + bz[0];
            r.y = p1.x + p1.y + bz[1];
            r.z = p2.x + p2.y + bz[2];
            r.w = p3.x + p3.y + bz[3];
            *reinterpret_cast<float4*>(out + (size_t)n * D + o0) = r;
        }
    }
}

// ---------------------------------------------------------------------------
// Launch. Inputs: x, edge_row, edge_col, pre_w, lin_w, bias, avg_deg_log
// ---------------------------------------------------------------------------
extern "C" void kernel_launch(void* const* d_in, const int* in_sizes, int n_in,
                              void* d_out, int out_size) {
    const float* x       = (const float*)d_in[0];
    const int*   erow    = (const int*)d_in[1];
    const int*   ecol    = (const int*)d_in[2];
    const float* pre_w   = (const float*)d_in[3];
    const float* lin_w   = (const float*)d_in[4];
    const float* bias    = (const float*)d_in[5];
    const float* avg_log = (const float*)d_in[6];

    const int N = in_sizes[0] / D;
    const int E = in_sizes[1];
    float* out = (float*)d_out;

    permute_zero_kernel<<<(N + 255) / 256, 256>>>(pre_w, lin_w, N);
    count_kernel<<<(E + 255) / 256, 256>>>(erow, E);
    int nsb = (N + SCAN_BLK - 1) / SCAN_BLK;
    scan_block_kernel<<<nsb, SCAN_BLK>>>(N);
    scan_top_kernel<<<1, 128>>>(nsb);
    scan_add_kernel<<<(N + 256) / 256, 256>>>(N, E);
    scatter_kernel<<<(E + 255) / 256, 256>>>(erow, ecol, E);

    {
        long long threads = (long long)N * 16;
        int blocks = (int)((threads + 255) / 256);
        aggregate_kernel<<<blocks, 256>>>(x, N);
    }

    {
        cudaFuncSetAttribute(finalize_kernel,
                             cudaFuncAttributeMaxDynamicSharedMemorySize,
                             FIN_SMEM);
        int blocks = (N + FIN_NODES - 1) / FIN_NODES;
        finalize_kernel<<<blocks, 256, FIN_SMEM>>>(
            x, bias, avg_log, out, N);
    }
}

// round 8
// speedup vs baseline: 1.0132x; 1.0132x over previous
#include <cuda_runtime.h>
#include <cuda_bf16.h>
#include <math.h>

#define D 64
#define EPSV 1e-7f
#define SCAN_BLK 1024
#define MAX_NODES 100000
#define MAX_EDGES 1600000
#define N_SCAN_BLKS ((MAX_NODES + SCAN_BLK - 1) / SCAN_BLK)   // 98

// Y tile geometry: 32 nodes, 224 k-pairs, row = 32 pairs + pad 2 = 34 u64
#define TILE_NODES 32
#define KKTOT 224
#define YROW 34                       // u64 per kk row (32 + 2 pad)
#define YBUF (KKTOT * YROW)           // 7616 u64 per buffer
#define FUSED_SMEM (2 * YBUF * 8)     // 121856 B

// Scratch (device globals; allocation is forbidden)
__device__ int   g_cnt[MAX_NODES];
__device__ int   g_rowptr[MAX_NODES + 1];
__device__ int   g_cur[MAX_NODES];
__device__ int   g_bsum[N_SCAN_BLKS];
__device__ int   g_csr[MAX_EDGES];
__device__ float g_wt[448 * 64];      // permuted weights (k-pair interleaved)

// ---------------------------------------------------------------------------
// K0: permute weights (lane-coalesced k-pair interleave) + zero g_cnt.
//   kk = k>>1, klo = k&1, og = o>>2, r = o&3
//   didx = kk*128 + (r>>1)*64 + og*4 + (r&1)*2 + klo
// GEMM reads ulonglong2 at u64x2 index kk*32+og (outs o0,o0+1 pairs) and
// kk*32+16+og (outs o0+2,o0+3).
// ---------------------------------------------------------------------------
__global__ void permute_zero_kernel(const float* __restrict__ pre_w,
                                    const float* __restrict__ lin_w, int N) {
    int idx = blockIdx.x * blockDim.x + threadIdx.x;
    if (idx < 448 * 64) {
        int k = idx >> 6;
        int o = idx & 63;
        int seg = k >> 6;
        int ki = k & 63;
        const float* W = (seg < 6) ? (pre_w + seg * 4096) : lin_w;
        float v = W[o * 64 + ki];
        int kk = k >> 1, klo = k & 1;
        int og = o >> 2, r = o & 3;
        int didx = kk * 128 + (r >> 1) * 64 + og * 4 + (r & 1) * 2 + klo;
        g_wt[didx] = v;
    }
    if (idx < N) g_cnt[idx] = 0;
}

// ---------------------------------------------------------------------------
// K1: histogram of destination degrees
// ---------------------------------------------------------------------------
__global__ void count_kernel(const int* __restrict__ erow, int E) {
    int e = blockIdx.x * blockDim.x + threadIdx.x;
    if (e < E) atomicAdd(&g_cnt[erow[e]], 1);
}

// ---------------------------------------------------------------------------
// K2a: per-block exclusive scan of g_cnt -> g_rowptr; block totals -> g_bsum
// ---------------------------------------------------------------------------
__global__ void scan_block_kernel(int n) {
    __shared__ int warp_sums[32];
    int i = blockIdx.x * SCAN_BLK + threadIdx.x;
    int v = (i < n) ? g_cnt[i] : 0;
    int lane = threadIdx.x & 31;
    int wid = threadIdx.x >> 5;

    int s = v;
    #pragma unroll
    for (int o = 1; o < 32; o <<= 1) {
        int t = __shfl_up_sync(0xffffffffu, s, o);
        if (lane >= o) s += t;
    }
    if (lane == 31) warp_sums[wid] = s;
    __syncthreads();
    if (wid == 0) {
        int ws = warp_sums[lane];
        #pragma unroll
        for (int o = 1; o < 32; o <<= 1) {
            int t = __shfl_up_sync(0xffffffffu, ws, o);
            if (lane >= o) ws += t;
        }
        warp_sums[lane] = ws;
    }
    __syncthreads();
    int warp_off = (wid == 0) ? 0 : warp_sums[wid - 1];
    if (i < n) g_rowptr[i] = warp_off + s - v;
    if (threadIdx.x == SCAN_BLK - 1) g_bsum[blockIdx.x] = warp_off + s;
}

// ---------------------------------------------------------------------------
// K2b: parallel exclusive scan of the 98 block sums
// ---------------------------------------------------------------------------
__global__ void scan_top_kernel(int nb) {
    __shared__ int sh[128];
    int t = threadIdx.x;
    int v = (t < nb) ? g_bsum[t] : 0;
    int lane = t & 31, wid = t >> 5;
    int s = v;
    #pragma unroll
    for (int o = 1; o < 32; o <<= 1) {
        int u = __shfl_up_sync(0xffffffffu, s, o);
        if (lane >= o) s += u;
    }
    if (lane == 31) sh[wid] = s;
    __syncthreads();
    if (t == 0) {
        int acc = 0;
        #pragma unroll
        for (int w = 0; w < 4; ++w) { int x = sh[w]; sh[w] = acc; acc += x; }
    }
    __syncthreads();
    if (t < nb) g_bsum[t] = sh[wid] + s - v;
}

// ---------------------------------------------------------------------------
// K2c: add block offsets; init cursors; rowptr[N] = E
// ---------------------------------------------------------------------------
__global__ void scan_add_kernel(int n, int E) {
    int i = blockIdx.x * blockDim.x + threadIdx.x;
    if (i < n) {
        int r = g_rowptr[i] + g_bsum[i >> 10];
        g_rowptr[i] = r;
        g_cur[i] = r;
    }
    if (i == n) g_rowptr[n] = E;
}

// ---------------------------------------------------------------------------
// K3: bucket-scatter edge sources into CSR
// ---------------------------------------------------------------------------
__global__ void scatter_kernel(const int* __restrict__ erow,
                               const int* __restrict__ ecol, int E) {
    int e = blockIdx.x * blockDim.x + threadIdx.x;
    if (e < E) {
        int d = erow[e];
        int pos = atomicAdd(&g_cur[d], 1);
        g_csr[pos] = ecol[e];
    }
}

// ---------------------------------------------------------------------------
// K4: persistent fused gather + GEMM.
// 384 threads: warps 0-3 produce (gather CSR neighbors, compute mean/std,
// fold degree factors, write transposed pair-major Y); warps 4-11 consume
// (FFMA2 GEMM against permuted weights). Double-buffered 32-node tiles.
// ---------------------------------------------------------------------------
__device__ __forceinline__ unsigned long long ffma2(
    unsigned long long a, unsigned long long b, unsigned long long c) {
    unsigned long long d;
    asm("fma.rn.f32x2 %0, %1, %2, %3;" : "=l"(d) : "l"(a), "l"(b), "l"(c));
    return d;
}

__device__ __forceinline__ void stage_tile(
    float2* Y2, int node0, int N, const float* __restrict__ x,
    float inv_avg, float avg, int stid)
{
    const int nl = stid >> 2;         // local node 0..31
    const int dpart = stid & 3;       // dim quarter: dims dpart*16..+15
    const int n = node0 + nl;

    float4 s1[4], s2[4];
    #pragma unroll
    for (int q = 0; q < 4; ++q) {
        s1[q] = make_float4(0.f, 0.f, 0.f, 0.f);
        s2[q] = make_float4(0.f, 0.f, 0.f, 0.f);
    }

    int beg = 0, end = 0;
    if (n < N) { beg = g_rowptr[n]; end = g_rowptr[n + 1]; }

    const float4* x4 = reinterpret_cast<const float4*>(x);
    for (int j = beg; j < end; ++j) {
        int s = __ldg(&g_csr[j]);
        const float4* xs = x4 + (size_t)s * 16 + dpart * 4;
        #pragma unroll
        for (int q = 0; q < 4; ++q) {
            float4 v = __ldg(xs + q);
            s1[q].x += v.x; s1[q].y += v.y; s1[q].z += v.z; s1[q].w += v.w;
            s2[q].x += v.x * v.x; s2[q].y += v.y * v.y;
            s2[q].z += v.z * v.z; s2[q].w += v.w * v.w;
        }
    }

    float4 xv[4];
    if (n < N) {
        #pragma unroll
        for (int q = 0; q < 4; ++q)
            xv[q] = __ldg(x4 + (size_t)n * 16 + dpart * 4 + q);
    } else {
        #pragma unroll
        for (int q = 0; q < 4; ++q) xv[q] = make_float4(0.f, 0.f, 0.f, 0.f);
    }

    float degf = (float)(end - beg);
    float logd = __logf(degf + 1.0f);
    float f1 = logd * inv_avg;
    float f2 = avg * __frcp_rn(logd + EPSV);

    const int ipbase = dpart * 8;     // pair index base within 32
    #pragma unroll
    for (int q = 0; q < 4; ++q) {
        float m[4]  = {s1[q].x, s1[q].y, s1[q].z, s1[q].w};
        float ss[4] = {s2[q].x, s2[q].y, s2[q].z, s2[q].w};
        float xr[4] = {xv[q].x, xv[q].y, xv[q].z, xv[q].w};
        float sd[4];
        #pragma unroll
        for (int c = 0; c < 4; ++c) {
            float v = fmaxf(ss[c] - m[c] * m[c], 0.f) + EPSV;
            sd[c] = v * rsqrtf(v);    // sqrt(v)
        }
        #pragma unroll
        for (int h = 0; h < 2; ++h) {
            int ip = ipbase + q * 2 + h;    // global pair 0..31 within seg
            float m0 = m[h * 2],  m1 = m[h * 2 + 1];
            float d0 = sd[h * 2], d1 = sd[h * 2 + 1];
            float x0 = xr[h * 2], x1 = xr[h * 2 + 1];
            Y2[(0 * 32 + ip) * YROW + nl] = make_float2(m0, m1);
            Y2[(1 * 32 + ip) * YROW + nl] = make_float2(f1 * m0, f1 * m1);
            Y2[(2 * 32 + ip) * YROW + nl] = make_float2(f2 * m0, f2 * m1);
            Y2[(3 * 32 + ip) * YROW + nl] = make_float2(d0, d1);
            Y2[(4 * 32 + ip) * YROW + nl] = make_float2(f1 * d0, f1 * d1);
            Y2[(5 * 32 + ip) * YROW + nl] = make_float2(f2 * d0, f2 * d1);
            Y2[(6 * 32 + ip) * YROW + nl] = make_float2(x0, x1);
        }
    }
}

__device__ __forceinline__ void gemm_tile(
    const unsigned long long* Yb, int node0, int N,
    const float* __restrict__ bias, float* __restrict__ out, int gtid)
{
    const int w = gtid >> 5;
    const int lane = gtid & 31;
    const int og = ((w & 1) << 3) | (lane & 7);      // 0..15 -> 4 outs each
    const int nb = ((w >> 1) << 3) + ((lane >> 3) << 1);  // even node offset
    const int o0 = og * 4;

    unsigned long long acc[2][4];
    #pragma unroll
    for (int a = 0; a < 2; ++a)
        #pragma unroll
        for (int q = 0; q < 4; ++q) acc[a][q] = 0ull;

    const ulonglong2* wb = reinterpret_cast<const ulonglong2*>(g_wt);

    #pragma unroll 4
    for (int kk = 0; kk < KKTOT; ++kk) {
        ulonglong2 y =
            *reinterpret_cast<const ulonglong2*>(Yb + kk * YROW + nb);
        ulonglong2 wlo = __ldg(wb + kk * 32 + og);        // outs o0, o0+1
        ulonglong2 whi = __ldg(wb + kk * 32 + 16 + og);   // outs o0+2, o0+3
        acc[0][0] = ffma2(y.x, wlo.x, acc[0][0]);
        acc[0][1] = ffma2(y.x, wlo.y, acc[0][1]);
        acc[0][2] = ffma2(y.x, whi.x, acc[0][2]);
        acc[0][3] = ffma2(y.x, whi.y, acc[0][3]);
        acc[1][0] = ffma2(y.y, wlo.x, acc[1][0]);
        acc[1][1] = ffma2(y.y, wlo.y, acc[1][1]);
        acc[1][2] = ffma2(y.y, whi.x, acc[1][2]);
        acc[1][3] = ffma2(y.y, whi.y, acc[1][3]);
    }

    float4 bz = __ldg(reinterpret_cast<const float4*>(bias) + og);

    #pragma unroll
    for (int a = 0; a < 2; ++a) {
        int n = node0 + nb + a;
        if (n < N) {
            float4 r;
            float2 p0 = *reinterpret_cast<float2*>(&acc[a][0]);
            float2 p1 = *reinterpret_cast<float2*>(&acc[a][1]);
            float2 p2 = *reinterpret_cast<float2*>(&acc[a][2]);
            float2 p3 = *reinterpret_cast<float2*>(&acc[a][3]);
            r.x = p0.x + p0.y + bz.x;
            r.y = p1.x + p1.y + bz.y;
            r.z = p2.x + p2.y + bz.z;
            r.w = p3.x + p3.y + bz.w;
            *reinterpret_cast<float4*>(out + (size_t)n * D + o0) = r;
        }
    }
}

__global__ void __launch_bounds__(384, 1)
fused_kernel(const float* __restrict__ x,
             const float* __restrict__ bias,
             const float* __restrict__ avg_ptr,
             float* __restrict__ out,
             int N, int ntiles)
{
    extern __shared__ unsigned long long Yt[];    // 2 * YBUF u64
    const int tid = threadIdx.x;
    const float avg = __ldg(avg_ptr);
    const float inv_avg = 1.0f / avg;

    int cur = 0;
    if ((int)blockIdx.x < ntiles && tid < 128)
        stage_tile(reinterpret_cast<float2*>(Yt), blockIdx.x * TILE_NODES,
                   N, x, inv_avg, avg, tid);
    __syncthreads();

    for (int t = blockIdx.x; t < ntiles; t += gridDim.x) {
        int nxt = t + gridDim.x;
        if (tid < 128) {
            if (nxt < ntiles)
                stage_tile(reinterpret_cast<float2*>(Yt + (cur ^ 1) * YBUF),
                           nxt * TILE_NODES, N, x, inv_avg, avg, tid);
        } else {
            gemm_tile(Yt + cur * YBUF, t * TILE_NODES, N, bias, out,
                      tid - 128);
        }
        __syncthreads();
        cur ^= 1;
    }
}

// ---------------------------------------------------------------------------
// Launch. Inputs: x, edge_row, edge_col, pre_w, lin_w, bias, avg_deg_log
// ---------------------------------------------------------------------------
extern "C" void kernel_launch(void* const* d_in, const int* in_sizes, int n_in,
                              void* d_out, int out_size) {
    const float* x       = (const float*)d_in[0];
    const int*   erow    = (const int*)d_in[1];
    const int*   ecol    = (const int*)d_in[2];
    const float* pre_w   = (const float*)d_in[3];
    const float* lin_w   = (const float*)d_in[4];
    const float* bias    = (const float*)d_in[5];
    const float* avg_log = (const float*)d_in[6];

    const int N = in_sizes[0] / D;
    const int E = in_sizes[1];
    float* out = (float*)d_out;

    permute_zero_kernel<<<(N + 255) / 256, 256>>>(pre_w, lin_w, N);
    count_kernel<<<(E + 255) / 256, 256>>>(erow, E);
    int nsb = (N + SCAN_BLK - 1) / SCAN_BLK;
    scan_block_kernel<<<nsb, SCAN_BLK>>>(N);
    scan_top_kernel<<<1, 128>>>(nsb);
    scan_add_kernel<<<(N + 256) / 256, 256>>>(N, E);
    scatter_kernel<<<(E + 255) / 256, 256>>>(erow, ecol, E);

    {
        static int nsm = 0;
        if (nsm == 0)
            cudaDeviceGetAttribute(&nsm, cudaDevAttrMultiProcessorCount, 0);
        int ntiles = (N + TILE_NODES - 1) / TILE_NODES;
        int grid = (nsm < ntiles) ? nsm : ntiles;
        cudaFuncSetAttribute(fused_kernel,
                             cudaFuncAttributeMaxDynamicSharedMemorySize,
                             FUSED_SMEM);
        fused_kernel<<<grid, 384, FUSED_SMEM>>>(x, bias, avg_log, out,
                                                N, ntiles);
    }
}

// round 9
// speedup vs baseline: 1.5130x; 1.4933x over previous
#include <cuda_runtime.h>
#include <cuda_bf16.h>
#include <math.h>

#define N_NODES 100000
#define N_EDGES 1600000
#define D 64
#define EPSV 1e-7f
#define SCAN_BLK 1024
#define N_SCAN_BLKS ((N_NODES + SCAN_BLK - 1) / SCAN_BLK)   // 98

// Scratch (device globals; allocation is forbidden)
__device__ float g_s1[N_NODES * D];
__device__ float g_s2[N_NODES * D];
__device__ int   g_cnt[N_NODES];
__device__ int   g_rowptr[N_NODES + 1];
__device__ int   g_cur[N_NODES];
__device__ int   g_bsum[N_SCAN_BLKS];
__device__ int   g_csr[N_EDGES];
__device__ float g_wt[448 * 64];     // permuted weights (k-pair interleaved)

// ---------------------------------------------------------------------------
// K0: permute weights (lane-coalesced k-pair interleave) + zero g_cnt.
//   kk = k>>1, klo = k&1, og = o>>2, r = o&3
//   didx = kk*128 + (r>>1)*64 + og*4 + (r&1)*2 + klo
// ---------------------------------------------------------------------------
__global__ void permute_zero_kernel(const float* __restrict__ pre_w,
                                    const float* __restrict__ lin_w, int N) {
    int idx = blockIdx.x * blockDim.x + threadIdx.x;
    if (idx < 448 * 64) {
        int k = idx >> 6;
        int o = idx & 63;
        int seg = k >> 6;
        int ki = k & 63;
        const float* W = (seg < 6) ? (pre_w + seg * 4096) : lin_w;
        float v = W[o * 64 + ki];
        int kk = k >> 1, klo = k & 1;
        int og = o >> 2, r = o & 3;
        int didx = kk * 128 + (r >> 1) * 64 + og * 4 + (r & 1) * 2 + klo;
        g_wt[didx] = v;
    }
    if (idx < N) g_cnt[idx] = 0;
}

// ---------------------------------------------------------------------------
// K1: histogram of destination degrees
// ---------------------------------------------------------------------------
__global__ void count_kernel(const int* __restrict__ erow, int E) {
    int e = blockIdx.x * blockDim.x + threadIdx.x;
    if (e < E) atomicAdd(&g_cnt[erow[e]], 1);
}

// ---------------------------------------------------------------------------
// K2a: per-block exclusive scan of g_cnt -> g_rowptr; block totals -> g_bsum
// ---------------------------------------------------------------------------
__global__ void scan_block_kernel(int n) {
    __shared__ int warp_sums[32];
    int i = blockIdx.x * SCAN_BLK + threadIdx.x;
    int v = (i < n) ? g_cnt[i] : 0;
    int lane = threadIdx.x & 31;
    int wid = threadIdx.x >> 5;

    int s = v;
    #pragma unroll
    for (int o = 1; o < 32; o <<= 1) {
        int t = __shfl_up_sync(0xffffffffu, s, o);
        if (lane >= o) s += t;
    }
    if (lane == 31) warp_sums[wid] = s;
    __syncthreads();
    if (wid == 0) {
        int ws = warp_sums[lane];
        #pragma unroll
        for (int o = 1; o < 32; o <<= 1) {
            int t = __shfl_up_sync(0xffffffffu, ws, o);
            if (lane >= o) ws += t;
        }
        warp_sums[lane] = ws;
    }
    __syncthreads();
    int warp_off = (wid == 0) ? 0 : warp_sums[wid - 1];
    if (i < n) g_rowptr[i] = warp_off + s - v;
    if (threadIdx.x == SCAN_BLK - 1) g_bsum[blockIdx.x] = warp_off + s;
}

// ---------------------------------------------------------------------------
// K2b: parallel exclusive scan of the 98 block sums
// ---------------------------------------------------------------------------
__global__ void scan_top_kernel(int nb) {
    __shared__ int sh[128];
    int t = threadIdx.x;
    int v = (t < nb) ? g_bsum[t] : 0;
    int lane = t & 31, wid = t >> 5;
    int s = v;
    #pragma unroll
    for (int o = 1; o < 32; o <<= 1) {
        int u = __shfl_up_sync(0xffffffffu, s, o);
        if (lane >= o) s += u;
    }
    if (lane == 31) sh[wid] = s;
    __syncthreads();
    if (t == 0) {
        int acc = 0;
        #pragma unroll
        for (int w = 0; w < 4; ++w) { int x = sh[w]; sh[w] = acc; acc += x; }
    }
    __syncthreads();
    if (t < nb) g_bsum[t] = sh[wid] + s - v;
}

// ---------------------------------------------------------------------------
// K2c: add block offsets; init cursors; rowptr[N] = E
// ---------------------------------------------------------------------------
__global__ void scan_add_kernel(int n, int E) {
    int i = blockIdx.x * blockDim.x + threadIdx.x;
    if (i < n) {
        int r = g_rowptr[i] + g_bsum[i >> 10];
        g_rowptr[i] = r;
        g_cur[i] = r;
    }
    if (i == n) g_rowptr[n] = E;
}

// ---------------------------------------------------------------------------
// K3: bucket-scatter edge sources into CSR
// ---------------------------------------------------------------------------
__global__ void scatter_kernel(const int* __restrict__ erow,
                               const int* __restrict__ ecol, int E) {
    int e = blockIdx.x * blockDim.x + threadIdx.x;
    if (e < E) {
        int d = erow[e];
        int pos = atomicAdd(&g_cur[d], 1);
        g_csr[pos] = ecol[e];
    }
}

// ---------------------------------------------------------------------------
// K4: gather-aggregate, 16 lanes/node, unrolled by 2 for MLP.
// ---------------------------------------------------------------------------
__global__ void aggregate_kernel(const float* __restrict__ x, int N) {
    int gid = blockIdx.x * blockDim.x + threadIdx.x;
    int n = gid >> 4;
    if (n >= N) return;
    int lane = gid & 15;

    int beg = g_rowptr[n];
    int end = g_rowptr[n + 1];

    float4 a = make_float4(0.f, 0.f, 0.f, 0.f);
    float4 b = make_float4(0.f, 0.f, 0.f, 0.f);
    const float4* x4 = reinterpret_cast<const float4*>(x);

    int j = beg;
    for (; j + 1 < end; j += 2) {
        int s0 = __ldg(&g_csr[j]);
        int s1 = __ldg(&g_csr[j + 1]);
        float4 v0 = __ldg(&x4[(size_t)s0 * 16 + lane]);
        float4 v1 = __ldg(&x4[(size_t)s1 * 16 + lane]);
        a.x += v0.x; a.y += v0.y; a.z += v0.z; a.w += v0.w;
        b.x += v0.x * v0.x; b.y += v0.y * v0.y;
        b.z += v0.z * v0.z; b.w += v0.w * v0.w;
        a.x += v1.x; a.y += v1.y; a.z += v1.z; a.w += v1.w;
        b.x += v1.x * v1.x; b.y += v1.y * v1.y;
        b.z += v1.z * v1.z; b.w += v1.w * v1.w;
    }
    if (j < end) {
        int s0 = __ldg(&g_csr[j]);
        float4 v0 = __ldg(&x4[(size_t)s0 * 16 + lane]);
        a.x += v0.x; a.y += v0.y; a.z += v0.z; a.w += v0.w;
        b.x += v0.x * v0.x; b.y += v0.y * v0.y;
        b.z += v0.z * v0.z; b.w += v0.w * v0.w;
    }

    size_t off = (size_t)n * 16 + lane;
    reinterpret_cast<float4*>(g_s1)[off] = a;
    reinterpret_cast<float4*>(g_s2)[off] = b;
}

// ---------------------------------------------------------------------------
// K5: finalize GEMM, FFMA2 packed along k (R5 config: 64 nodes/CTA).
// 256 threads: og = tid&15 (4 outs), ng = tid>>4 (4 nodes).
// Staging uses fast-math MUFU forms (rsqrtf/__logf/__frcp_rn).
// ---------------------------------------------------------------------------
__device__ __forceinline__ unsigned long long ffma2(
    unsigned long long a, unsigned long long b, unsigned long long c) {
    unsigned long long d;
    asm("fma.rn.f32x2 %0, %1, %2, %3;" : "=l"(d) : "l"(a), "l"(b), "l"(c));
    return d;
}

__global__ void __launch_bounds__(256, 1)
finalize_kernel(const float* __restrict__ x,
                const float* __restrict__ bias,
                const float* __restrict__ avg_ptr,
                float* __restrict__ out,
                int N) {
    extern __shared__ float Ysh[];                 // [64][448]
    __shared__ float f1s[64], f2s[64];
    const int tid = threadIdx.x;
    const int node0 = blockIdx.x * 64;

    if (tid < 64) {
        int n = node0 + tid;
        float f1 = 0.f, f2 = 0.f;
        if (n < N) {
            float avg = __ldg(avg_ptr);
            float degf = (float)(g_rowptr[n + 1] - g_rowptr[n]);
            float logd = __logf(degf + 1.0f);
            f1 = logd * __frcp_rn(avg);
            f2 = avg * __frcp_rn(logd + EPSV);
        }
        f1s[tid] = f1;
        f2s[tid] = f2;
    }
    __syncthreads();

    #pragma unroll
    for (int t = 0; t < 16; ++t) {
        int p = tid + t * 256;
        int nl = p >> 6;
        int i = p & 63;
        int n = node0 + nl;
        float mean = 0.f, stdv = 0.f, xv = 0.f;
        if (n < N) {
            mean = g_s1[(size_t)n * D + i];
            float s2v = g_s2[(size_t)n * D + i];
            float v = fmaxf(s2v - mean * mean, 0.f) + EPSV;
            stdv = v * rsqrtf(v);            // sqrt(v): 1 MUFU + 1 FMUL
            xv = __ldg(x + (size_t)n * D + i);
        }
        float f1 = f1s[nl], f2 = f2s[nl];
        float* Yr = Ysh + nl * 448;
        Yr[i]       = mean;
        Yr[64 + i]  = f1 * mean;
        Yr[128 + i] = f2 * mean;
        Yr[192 + i] = stdv;
        Yr[256 + i] = f1 * stdv;
        Yr[320 + i] = f2 * stdv;
        Yr[384 + i] = xv;
    }
    __syncthreads();

    const int og = tid & 15;
    const int ng = tid >> 4;
    const int o0 = og * 4;
    const int na = ng * 4;

    unsigned long long acc[4][4];
    #pragma unroll
    for (int j = 0; j < 4; ++j)
        #pragma unroll
        for (int q = 0; q < 4; ++q) acc[j][q] = 0ull;

    const ulonglong2* wbase = reinterpret_cast<const ulonglong2*>(g_wt);
    const unsigned long long* Y0 =
        reinterpret_cast<const unsigned long long*>(Ysh + na * 448);
    const unsigned long long* Y1 =
        reinterpret_cast<const unsigned long long*>(Ysh + (na + 1) * 448);
    const unsigned long long* Y2 =
        reinterpret_cast<const unsigned long long*>(Ysh + (na + 2) * 448);
    const unsigned long long* Y3 =
        reinterpret_cast<const unsigned long long*>(Ysh + (na + 3) * 448);

    #pragma unroll 4
    for (int kk = 0; kk < 224; ++kk) {
        ulonglong2 wlo = __ldg(wbase + kk * 32 + og);         // pairs o0, o0+1
        ulonglong2 whi = __ldg(wbase + kk * 32 + 16 + og);    // pairs o0+2, o0+3
        unsigned long long y0 = Y0[kk];
        unsigned long long y1 = Y1[kk];
        unsigned long long y2 = Y2[kk];
        unsigned long long y3 = Y3[kk];
        acc[0][0] = ffma2(y0, wlo.x, acc[0][0]);
        acc[0][1] = ffma2(y0, wlo.y, acc[0][1]);
        acc[0][2] = ffma2(y0, whi.x, acc[0][2]);
        acc[0][3] = ffma2(y0, whi.y, acc[0][3]);
        acc[1][0] = ffma2(y1, wlo.x, acc[1][0]);
        acc[1][1] = ffma2(y1, wlo.y, acc[1][1]);
        acc[1][2] = ffma2(y1, whi.x, acc[1][2]);
        acc[1][3] = ffma2(y1, whi.y, acc[1][3]);
        acc[2][0] = ffma2(y2, wlo.x, acc[2][0]);
        acc[2][1] = ffma2(y2, wlo.y, acc[2][1]);
        acc[2][2] = ffma2(y2, whi.x, acc[2][2]);
        acc[2][3] = ffma2(y2, whi.y, acc[2][3]);
        acc[3][0] = ffma2(y3, wlo.x, acc[3][0]);
        acc[3][1] = ffma2(y3, wlo.y, acc[3][1]);
        acc[3][2] = ffma2(y3, whi.x, acc[3][2]);
        acc[3][3] = ffma2(y3, whi.y, acc[3][3]);
    }

    float bz[4];
    #pragma unroll
    for (int q = 0; q < 4; ++q) bz[q] = __ldg(bias + o0 + q);

    #pragma unroll
    for (int j = 0; j < 4; ++j) {
        int n = node0 + na + j;
        if (n < N) {
            float4 r;
            float2 p0 = *reinterpret_cast<float2*>(&acc[j][0]);
            float2 p1 = *reinterpret_cast<float2*>(&acc[j][1]);
            float2 p2 = *reinterpret_cast<float2*>(&acc[j][2]);
            float2 p3 = *reinterpret_cast<float2*>(&acc[j][3]);
            r.x = p0.x + p0.y + bz[0];
            r.y = p1.x + p1.y + bz[1];
            r.z = p2.x + p2.y + bz[2];
            r.w = p3.x + p3.y + bz[3];
            *reinterpret_cast<float4*>(out + (size_t)n * D + o0) = r;
        }
    }
}

// ---------------------------------------------------------------------------
// Launch. Inputs: x, edge_row, edge_col, pre_w, lin_w, bias, avg_deg_log
// ---------------------------------------------------------------------------
extern "C" void kernel_launch(void* const* d_in, const int* in_sizes, int n_in,
                              void* d_out, int out_size) {
    const float* x       = (const float*)d_in[0];
    const int*   erow    = (const int*)d_in[1];
    const int*   ecol    = (const int*)d_in[2];
    const float* pre_w   = (const float*)d_in[3];
    const float* lin_w   = (const float*)d_in[4];
    const float* bias    = (const float*)d_in[5];
    const float* avg_log = (const float*)d_in[6];

    const int N = in_sizes[0] / D;
    const int E = in_sizes[1];
    float* out = (float*)d_out;

    permute_zero_kernel<<<(N + 255) / 256, 256>>>(pre_w, lin_w, N);
    count_kernel<<<(E + 255) / 256, 256>>>(erow, E);
    int nsb = (N + SCAN_BLK - 1) / SCAN_BLK;
    scan_block_kernel<<<nsb, SCAN_BLK>>>(N);
    scan_top_kernel<<<1, 128>>>(nsb);
    scan_add_kernel<<<(N + 256) / 256, 256>>>(N, E);
    scatter_kernel<<<(E + 255) / 256, 256>>>(erow, ecol, E);

    {
        long long threads = (long long)N * 16;
        int blocks = (int)((threads + 255) / 256);
        aggregate_kernel<<<blocks, 256>>>(x, N);
    }

    {
        cudaFuncSetAttribute(finalize_kernel,
                             cudaFuncAttributeMaxDynamicSharedMemorySize,
                             64 * 448 * 4);
        int blocks = (N + 63) / 64;
        finalize_kernel<<<blocks, 256, 64 * 448 * 4>>>(
            x, bias, avg_log, out, N);
    }
}

// round 10
// speedup vs baseline: 1.5234x; 1.0069x over previous
#include <cuda_runtime.h>
#include <cuda_bf16.h>
#include <math.h>

#define N_NODES 100000
#define N_EDGES 1600000
#define D 64
#define EPSV 1e-7f
#define SCAN_BLK 1024
#define N_SCAN_BLKS ((N_NODES + SCAN_BLK - 1) / SCAN_BLK)   // 98

// Scratch (device globals; allocation is forbidden)
__device__ float g_s1[N_NODES * D];
__device__ float g_s2[N_NODES * D];
__device__ int   g_cnt[N_NODES];
__device__ int   g_rowptr[N_NODES + 1];
__device__ int   g_rank[N_EDGES];
__device__ int   g_bsum[N_SCAN_BLKS];
__device__ int   g_csr[N_EDGES];
__device__ float g_wt[448 * 64];     // permuted weights (k-pair interleaved)

// ---------------------------------------------------------------------------
// K0: permute weights (lane-coalesced k-pair interleave) + zero g_cnt.
// ---------------------------------------------------------------------------
__global__ void permute_zero_kernel(const float* __restrict__ pre_w,
                                    const float* __restrict__ lin_w, int N) {
    int idx = blockIdx.x * blockDim.x + threadIdx.x;
    if (idx < 448 * 64) {
        int k = idx >> 6;
        int o = idx & 63;
        int seg = k >> 6;
        int ki = k & 63;
        const float* W = (seg < 6) ? (pre_w + seg * 4096) : lin_w;
        float v = W[o * 64 + ki];
        int kk = k >> 1, klo = k & 1;
        int og = o >> 2, r = o & 3;
        int didx = kk * 128 + (r >> 1) * 64 + og * 4 + (r & 1) * 2 + klo;
        g_wt[didx] = v;
    }
    if (idx < N) g_cnt[idx] = 0;
}

// ---------------------------------------------------------------------------
// K1: histogram + per-edge rank (the only atomic pass)
// ---------------------------------------------------------------------------
__global__ void count_rank_kernel(const int* __restrict__ erow, int E) {
    int e = blockIdx.x * blockDim.x + threadIdx.x;
    if (e < E) g_rank[e] = atomicAdd(&g_cnt[erow[e]], 1);
}

// ---------------------------------------------------------------------------
// K2a: per-block exclusive scan of g_cnt -> g_rowptr; block totals -> g_bsum
// ---------------------------------------------------------------------------
__global__ void scan_block_kernel(int n) {
    __shared__ int warp_sums[32];
    int i = blockIdx.x * SCAN_BLK + threadIdx.x;
    int v = (i < n) ? g_cnt[i] : 0;
    int lane = threadIdx.x & 31;
    int wid = threadIdx.x >> 5;

    int s = v;
    #pragma unroll
    for (int o = 1; o < 32; o <<= 1) {
        int t = __shfl_up_sync(0xffffffffu, s, o);
        if (lane >= o) s += t;
    }
    if (lane == 31) warp_sums[wid] = s;
    __syncthreads();
    if (wid == 0) {
        int ws = warp_sums[lane];
        #pragma unroll
        for (int o = 1; o < 32; o <<= 1) {
            int t = __shfl_up_sync(0xffffffffu, ws, o);
            if (lane >= o) ws += t;
        }
        warp_sums[lane] = ws;
    }
    __syncthreads();
    int warp_off = (wid == 0) ? 0 : warp_sums[wid - 1];
    if (i < n) g_rowptr[i] = warp_off + s - v;
    if (threadIdx.x == SCAN_BLK - 1) g_bsum[blockIdx.x] = warp_off + s;
}

// ---------------------------------------------------------------------------
// K2b: parallel exclusive scan of the 98 block sums
// ---------------------------------------------------------------------------
__global__ void scan_top_kernel(int nb) {
    __shared__ int sh[128];
    int t = threadIdx.x;
    int v = (t < nb) ? g_bsum[t] : 0;
    int lane = t & 31, wid = t >> 5;
    int s = v;
    #pragma unroll
    for (int o = 1; o < 32; o <<= 1) {
        int u = __shfl_up_sync(0xffffffffu, s, o);
        if (lane >= o) s += u;
    }
    if (lane == 31) sh[wid] = s;
    __syncthreads();
    if (t == 0) {
        int acc = 0;
        #pragma unroll
        for (int w = 0; w < 4; ++w) { int x = sh[w]; sh[w] = acc; acc += x; }
    }
    __syncthreads();
    if (t < nb) g_bsum[t] = sh[wid] + s - v;
}

// ---------------------------------------------------------------------------
// K2c: add block offsets; rowptr[N] = E
// ---------------------------------------------------------------------------
__global__ void scan_add_kernel(int n, int E) {
    int i = blockIdx.x * blockDim.x + threadIdx.x;
    if (i < n) g_rowptr[i] += g_bsum[i >> 10];
    if (i == n) g_rowptr[n] = E;
}

// ---------------------------------------------------------------------------
// K3: atomic-free scatter using precomputed ranks
// ---------------------------------------------------------------------------
__global__ void scatter_kernel(const int* __restrict__ erow,
                               const int* __restrict__ ecol, int E) {
    int e = blockIdx.x * blockDim.x + threadIdx.x;
    if (e < E) {
        int d = erow[e];
        int pos = __ldg(&g_rowptr[d]) + g_rank[e];
        g_csr[pos] = ecol[e];
    }
}

// ---------------------------------------------------------------------------
// K4: gather-aggregate, 16 lanes/node, unrolled by 2 for MLP.
// ---------------------------------------------------------------------------
__global__ void aggregate_kernel(const float* __restrict__ x, int N) {
    int gid = blockIdx.x * blockDim.x + threadIdx.x;
    int n = gid >> 4;
    if (n >= N) return;
    int lane = gid & 15;

    int beg = g_rowptr[n];
    int end = g_rowptr[n + 1];

    float4 a = make_float4(0.f, 0.f, 0.f, 0.f);
    float4 b = make_float4(0.f, 0.f, 0.f, 0.f);
    const float4* x4 = reinterpret_cast<const float4*>(x);

    int j = beg;
    for (; j + 1 < end; j += 2) {
        int s0 = __ldg(&g_csr[j]);
        int s1 = __ldg(&g_csr[j + 1]);
        float4 v0 = __ldg(&x4[(size_t)s0 * 16 + lane]);
        float4 v1 = __ldg(&x4[(size_t)s1 * 16 + lane]);
        a.x += v0.x; a.y += v0.y; a.z += v0.z; a.w += v0.w;
        b.x += v0.x * v0.x; b.y += v0.y * v0.y;
        b.z += v0.z * v0.z; b.w += v0.w * v0.w;
        a.x += v1.x; a.y += v1.y; a.z += v1.z; a.w += v1.w;
        b.x += v1.x * v1.x; b.y += v1.y * v1.y;
        b.z += v1.z * v1.z; b.w += v1.w * v1.w;
    }
    if (j < end) {
        int s0 = __ldg(&g_csr[j]);
        float4 v0 = __ldg(&x4[(size_t)s0 * 16 + lane]);
        a.x += v0.x; a.y += v0.y; a.z += v0.z; a.w += v0.w;
        b.x += v0.x * v0.x; b.y += v0.y * v0.y;
        b.z += v0.z * v0.z; b.w += v0.w * v0.w;
    }

    size_t off = (size_t)n * 16 + lane;
    reinterpret_cast<float4*>(g_s1)[off] = a;
    reinterpret_cast<float4*>(g_s2)[off] = b;
}

// ---------------------------------------------------------------------------
// K5: finalize GEMM, FFMA2 packed along k (64 nodes/CTA).
// ---------------------------------------------------------------------------
__device__ __forceinline__ unsigned long long ffma2(
    unsigned long long a, unsigned long long b, unsigned long long c) {
    unsigned long long d;
    asm("fma.rn.f32x2 %0, %1, %2, %3;" : "=l"(d) : "l"(a), "l"(b), "l"(c));
    return d;
}

__global__ void __launch_bounds__(256, 1)
finalize_kernel(const float* __restrict__ x,
                const float* __restrict__ bias,
                const float* __restrict__ avg_ptr,
                float* __restrict__ out,
                int N) {
    extern __shared__ float Ysh[];                 // [64][448]
    __shared__ float f1s[64], f2s[64];
    const int tid = threadIdx.x;
    const int node0 = blockIdx.x * 64;

    if (tid < 64) {
        int n = node0 + tid;
        float f1 = 0.f, f2 = 0.f;
        if (n < N) {
            float avg = __ldg(avg_ptr);
            float degf = (float)(g_rowptr[n + 1] - g_rowptr[n]);
            float logd = __logf(degf + 1.0f);
            f1 = logd * __frcp_rn(avg);
            f2 = avg * __frcp_rn(logd + EPSV);
        }
        f1s[tid] = f1;
        f2s[tid] = f2;
    }
    __syncthreads();

    #pragma unroll
    for (int t = 0; t < 16; ++t) {
        int p = tid + t * 256;
        int nl = p >> 6;
        int i = p & 63;
        int n = node0 + nl;
        float mean = 0.f, stdv = 0.f, xv = 0.f;
        if (n < N) {
            mean = g_s1[(size_t)n * D + i];
            float s2v = g_s2[(size_t)n * D + i];
            float v = fmaxf(s2v - mean * mean, 0.f) + EPSV;
            stdv = v * rsqrtf(v);            // sqrt(v): 1 MUFU + 1 FMUL
            xv = __ldg(x + (size_t)n * D + i);
        }
        float f1 = f1s[nl], f2 = f2s[nl];
        float* Yr = Ysh + nl * 448;
        Yr[i]       = mean;
        Yr[64 + i]  = f1 * mean;
        Yr[128 + i] = f2 * mean;
        Yr[192 + i] = stdv;
        Yr[256 + i] = f1 * stdv;
        Yr[320 + i] = f2 * stdv;
        Yr[384 + i] = xv;
    }
    __syncthreads();

    const int og = tid & 15;
    const int ng = tid >> 4;
    const int o0 = og * 4;
    const int na = ng * 4;

    unsigned long long acc[4][4];
    #pragma unroll
    for (int j = 0; j < 4; ++j)
        #pragma unroll
        for (int q = 0; q < 4; ++q) acc[j][q] = 0ull;

    const ulonglong2* wbase = reinterpret_cast<const ulonglong2*>(g_wt);
    const unsigned long long* Y0 =
        reinterpret_cast<const unsigned long long*>(Ysh + na * 448);
    const unsigned long long* Y1 =
        reinterpret_cast<const unsigned long long*>(Ysh + (na + 1) * 448);
    const unsigned long long* Y2 =
        reinterpret_cast<const unsigned long long*>(Ysh + (na + 2) * 448);
    const unsigned long long* Y3 =
        reinterpret_cast<const unsigned long long*>(Ysh + (na + 3) * 448);

    #pragma unroll 4
    for (int kk = 0; kk < 224; ++kk) {
        ulonglong2 wlo = __ldg(wbase + kk * 32 + og);         // pairs o0, o0+1
        ulonglong2 whi = __ldg(wbase + kk * 32 + 16 + og);    // pairs o0+2, o0+3
        unsigned long long y0 = Y0[kk];
        unsigned long long y1 = Y1[kk];
        unsigned long long y2 = Y2[kk];
        unsigned long long y3 = Y3[kk];
        acc[0][0] = ffma2(y0, wlo.x, acc[0][0]);
        acc[0][1] = ffma2(y0, wlo.y, acc[0][1]);
        acc[0][2] = ffma2(y0, whi.x, acc[0][2]);
        acc[0][3] = ffma2(y0, whi.y, acc[0][3]);
        acc[1][0] = ffma2(y1, wlo.x, acc[1][0]);
        acc[1][1] = ffma2(y1, wlo.y, acc[1][1]);
        acc[1][2] = ffma2(y1, whi.x, acc[1][2]);
        acc[1][3] = ffma2(y1, whi.y, acc[1][3]);
        acc[2][0] = ffma2(y2, wlo.x, acc[2][0]);
        acc[2][1] = ffma2(y2, wlo.y, acc[2][1]);
        acc[2][2] = ffma2(y2, whi.x, acc[2][2]);
        acc[2][3] = ffma2(y2, whi.y, acc[2][3]);
        acc[3][0] = ffma2(y3, wlo.x, acc[3][0]);
        acc[3][1] = ffma2(y3, wlo.y, acc[3][1]);
        acc[3][2] = ffma2(y3, whi.x, acc[3][2]);
        acc[3][3] = ffma2(y3, whi.y, acc[3][3]);
    }

    float bz[4];
    #pragma unroll
    for (int q = 0; q < 4; ++q) bz[q] = __ldg(bias + o0 + q);

    #pragma unroll
    for (int j = 0; j < 4; ++j) {
        int n = node0 + na + j;
        if (n < N) {
            float4 r;
            float2 p0 = *reinterpret_cast<float2*>(&acc[j][0]);
            float2 p1 = *reinterpret_cast<float2*>(&acc[j][1]);
            float2 p2 = *reinterpret_cast<float2*>(&acc[j][2]);
            float2 p3 = *reinterpret_cast<float2*>(&acc[j][3]);
            r.x = p0.x + p0.y + bz[0];
            r.y = p1.x + p1.y + bz[1];
            r.z = p2.x + p2.y + bz[2];
            r.w = p3.x + p3.y + bz[3];
            *reinterpret_cast<float4*>(out + (size_t)n * D + o0) = r;
        }
    }
}

// ---------------------------------------------------------------------------
// Launch. Inputs: x, edge_row, edge_col, pre_w, lin_w, bias, avg_deg_log
// ---------------------------------------------------------------------------
extern "C" void kernel_launch(void* const* d_in, const int* in_sizes, int n_in,
                              void* d_out, int out_size) {
    const float* x       = (const float*)d_in[0];
    const int*   erow    = (const int*)d_in[1];
    const int*   ecol    = (const int*)d_in[2];
    const float* pre_w   = (const float*)d_in[3];
    const float* lin_w   = (const float*)d_in[4];
    const float* bias    = (const float*)d_in[5];
    const float* avg_log = (const float*)d_in[6];

    const int N = in_sizes[0] / D;
    const int E = in_sizes[1];
    float* out = (float*)d_out;

    permute_zero_kernel<<<(N + 255) / 256, 256>>>(pre_w, lin_w, N);
    count_rank_kernel<<<(E + 255) / 256, 256>>>(erow, E);
    int nsb = (N + SCAN_BLK - 1) / SCAN_BLK;
    scan_block_kernel<<<nsb, SCAN_BLK>>>(N);
    scan_top_kernel<<<1, 128>>>(nsb);
    scan_add_kernel<<<(N + 256) / 256, 256>>>(N, E);
    scatter_kernel<<<(E + 255) / 256, 256>>>(erow, ecol, E);

    {
        long long threads = (long long)N * 16;
        int blocks = (int)((threads + 255) / 256);
        aggregate_kernel<<<blocks, 256>>>(x, N);
    }

    {
        cudaFuncSetAttribute(finalize_kernel,
                             cudaFuncAttributeMaxDynamicSharedMemorySize,
                             64 * 448 * 4);
        int blocks = (N + 63) / 64;
        finalize_kernel<<<blocks, 256, 64 * 448 * 4>>>(
            x, bias, avg_log, out, N);
    }
}

// round 12
// speedup vs baseline: 1.5611x; 1.0248x over previous
#include <cuda_runtime.h>
#include <cuda_bf16.h>
#include <math.h>
#include <stdint.h>

#define N_NODES 100000
#define N_EDGES 1600000
#define D 64
#define EPSV 1e-7f
#define SCAN_BLK 1024
#define N_SCAN_BLKS ((N_NODES + SCAN_BLK - 1) / SCAN_BLK)   // 98

// ---- mma finalize geometry ----
#define TM 64                       // nodes per CTA tile
#define KSTEPS 28                   // 448 / 16
#define YSTRIDE 456                 // bf16 per Y row (448 + 8 pad) -> conflict-free
#define YBYTES (TM * YSTRIDE * 2)   // 58368 B per array
#define FIN_SMEM (2 * YBYTES)       // Yh + Yl = 116736 B

// Scratch (device globals; allocation is forbidden)
__device__ float g_s1[N_NODES * D];
__device__ float g_s2[N_NODES * D];
__device__ int   g_cnt[N_NODES];
__device__ int   g_rowptr[N_NODES + 1];
__device__ int   g_rank[N_EDGES];
__device__ int   g_bsum[N_SCAN_BLKS];
__device__ int   g_csr[N_EDGES];
// fragment-packed weights: [kstep s][nfrag fg][lane] -> u64 (b0 | b1<<32)
__device__ unsigned long long g_wfh[KSTEPS * 8 * 32];
__device__ unsigned long long g_wfl[KSTEPS * 8 * 32];

__device__ __forceinline__ unsigned short bf2us(__nv_bfloat16 h) {
    return *reinterpret_cast<unsigned short*>(&h);
}
__device__ __forceinline__ void bf16_split(float v, __nv_bfloat16& h,
                                           __nv_bfloat16& l) {
    h = __float2bfloat16_rn(v);
    l = __float2bfloat16_rn(v - __bfloat162float(h));
}

// ---------------------------------------------------------------------------
// K0: pack weights into mma fragment layout (hi/lo) + zero g_cnt.
// Wcat(o, k): seg = k>>6 (0..6): seg<6 -> pre_w[(seg*64+o)*64 + (k&63)]
//             (seg = aggr*3 + scaler matches Y segment order), else lin_w.
// For (s, fg, lane): g = lane>>2, tg = lane&3, o = fg*8+g, k0 = s*16+tg*2.
//   b0 = pack(W(o,k0), W(o,k0+1)); b1 = pack(W(o,k0+8), W(o,k0+9)).
// ---------------------------------------------------------------------------
__device__ __forceinline__ float wcat(const float* __restrict__ pre_w,
                                      const float* __restrict__ lin_w,
                                      int o, int k) {
    int seg = k >> 6;
    int ki = k & 63;
    return (seg < 6) ? __ldg(pre_w + (seg * 64 + o) * 64 + ki)
                     : __ldg(lin_w + o * 64 + ki);
}

__global__ void permute_zero_kernel(const float* __restrict__ pre_w,
                                    const float* __restrict__ lin_w, int N) {
    int idx = blockIdx.x * blockDim.x + threadIdx.x;
    if (idx < KSTEPS * 8 * 32) {
        int lane = idx & 31;
        int fg = (idx >> 5) & 7;
        int s = idx >> 8;
        int g = lane >> 2, tg = lane & 3;
        int o = fg * 8 + g;
        int k0 = s * 16 + tg * 2;
        float v0 = wcat(pre_w, lin_w, o, k0);
        float v1 = wcat(pre_w, lin_w, o, k0 + 1);
        float v8 = wcat(pre_w, lin_w, o, k0 + 8);
        float v9 = wcat(pre_w, lin_w, o, k0 + 9);
        __nv_bfloat16 h, l;
        uint32_t bh0, bh1, bl0, bl1;
        bf16_split(v0, h, l); bh0 = bf2us(h);        bl0 = bf2us(l);
        bf16_split(v1, h, l); bh0 |= (uint32_t)bf2us(h) << 16;
                              bl0 |= (uint32_t)bf2us(l) << 16;
        bf16_split(v8, h, l); bh1 = bf2us(h);        bl1 = bf2us(l);
        bf16_split(v9, h, l); bh1 |= (uint32_t)bf2us(h) << 16;
                              bl1 |= (uint32_t)bf2us(l) << 16;
        g_wfh[idx] = (unsigned long long)bh0 |
                     ((unsigned long long)bh1 << 32);
        g_wfl[idx] = (unsigned long long)bl0 |
                     ((unsigned long long)bl1 << 32);
    }
    if (idx < N) g_cnt[idx] = 0;
}

// ---------------------------------------------------------------------------
// K1: histogram + per-edge rank (the only atomic pass)
// ---------------------------------------------------------------------------
__global__ void count_rank_kernel(const int* __restrict__ erow, int E) {
    int e = blockIdx.x * blockDim.x + threadIdx.x;
    if (e < E) g_rank[e] = atomicAdd(&g_cnt[erow[e]], 1);
}

// ---------------------------------------------------------------------------
// K2a/b/c: device-wide exclusive scan
// ---------------------------------------------------------------------------
__global__ void scan_block_kernel(int n) {
    __shared__ int warp_sums[32];
    int i = blockIdx.x * SCAN_BLK + threadIdx.x;
    int v = (i < n) ? g_cnt[i] : 0;
    int lane = threadIdx.x & 31;
    int wid = threadIdx.x >> 5;

    int s = v;
    #pragma unroll
    for (int o = 1; o < 32; o <<= 1) {
        int t = __shfl_up_sync(0xffffffffu, s, o);
        if (lane >= o) s += t;
    }
    if (lane == 31) warp_sums[wid] = s;
    __syncthreads();
    if (wid == 0) {
        int ws = warp_sums[lane];
        #pragma unroll
        for (int o = 1; o < 32; o <<= 1) {
            int t = __shfl_up_sync(0xffffffffu, ws, o);
            if (lane >= o) ws += t;
        }
        warp_sums[lane] = ws;
    }
    __syncthreads();
    int warp_off = (wid == 0) ? 0 : warp_sums[wid - 1];
    if (i < n) g_rowptr[i] = warp_off + s - v;
    if (threadIdx.x == SCAN_BLK - 1) g_bsum[blockIdx.x] = warp_off + s;
}

__global__ void scan_top_kernel(int nb) {
    __shared__ int sh[128];
    int t = threadIdx.x;
    int v = (t < nb) ? g_bsum[t] : 0;
    int lane = t & 31, wid = t >> 5;
    int s = v;
    #pragma unroll
    for (int o = 1; o < 32; o <<= 1) {
        int u = __shfl_up_sync(0xffffffffu, s, o);
        if (lane >= o) s += u;
    }
    if (lane == 31) sh[wid] = s;
    __syncthreads();
    if (t == 0) {
        int acc = 0;
        #pragma unroll
        for (int w = 0; w < 4; ++w) { int x = sh[w]; sh[w] = acc; acc += x; }
    }
    __syncthreads();
    if (t < nb) g_bsum[t] = sh[wid] + s - v;
}

__global__ void scan_add_kernel(int n, int E) {
    int i = blockIdx.x * blockDim.x + threadIdx.x;
    if (i < n) g_rowptr[i] += g_bsum[i >> 10];
    if (i == n) g_rowptr[n] = E;
}

// ---------------------------------------------------------------------------
// K3: atomic-free scatter using precomputed ranks
// ---------------------------------------------------------------------------
__global__ void scatter_kernel(const int* __restrict__ erow,
                               const int* __restrict__ ecol, int E) {
    int e = blockIdx.x * blockDim.x + threadIdx.x;
    if (e < E) {
        int d = erow[e];
        int pos = __ldg(&g_rowptr[d]) + g_rank[e];
        g_csr[pos] = ecol[e];
    }
}

// ---------------------------------------------------------------------------
// K4: gather-aggregate, 16 lanes/node, unrolled by 2 for MLP.
// ---------------------------------------------------------------------------
__global__ void aggregate_kernel(const float* __restrict__ x, int N) {
    int gid = blockIdx.x * blockDim.x + threadIdx.x;
    int n = gid >> 4;
    if (n >= N) return;
    int lane = gid & 15;

    int beg = g_rowptr[n];
    int end = g_rowptr[n + 1];

    float4 a = make_float4(0.f, 0.f, 0.f, 0.f);
    float4 b = make_float4(0.f, 0.f, 0.f, 0.f);
    const float4* x4 = reinterpret_cast<const float4*>(x);

    int j = beg;
    for (; j + 1 < end; j += 2) {
        int s0 = __ldg(&g_csr[j]);
        int s1 = __ldg(&g_csr[j + 1]);
        float4 v0 = __ldg(&x4[(size_t)s0 * 16 + lane]);
        float4 v1 = __ldg(&x4[(size_t)s1 * 16 + lane]);
        a.x += v0.x; a.y += v0.y; a.z += v0.z; a.w += v0.w;
        b.x += v0.x * v0.x; b.y += v0.y * v0.y;
        b.z += v0.z * v0.z; b.w += v0.w * v0.w;
        a.x += v1.x; a.y += v1.y; a.z += v1.z; a.w += v1.w;
        b.x += v1.x * v1.x; b.y += v1.y * v1.y;
        b.z += v1.z * v1.z; b.w += v1.w * v1.w;
    }
    if (j < end) {
        int s0 = __ldg(&g_csr[j]);
        float4 v0 = __ldg(&x4[(size_t)s0 * 16 + lane]);
        a.x += v0.x; a.y += v0.y; a.z += v0.z; a.w += v0.w;
        b.x += v0.x * v0.x; b.y += v0.y * v0.y;
        b.z += v0.z * v0.z; b.w += v0.w * v0.w;
    }

    size_t off = (size_t)n * 16 + lane;
    reinterpret_cast<float4*>(g_s1)[off] = a;
    reinterpret_cast<float4*>(g_s2)[off] = b;
}

// ---------------------------------------------------------------------------
// K5: finalize via mma.sync m16n8k16 bf16 (3-pass hi/lo split).
// 64 nodes/CTA, 256 threads = 8 warps: mi = wid&3 (16-node group),
// nh = wid>>2 (32-out half). Y staged factor-folded (K=448) as bf16 hi/lo.
// ---------------------------------------------------------------------------
__device__ __forceinline__ void mma16816(float& c0, float& c1, float& c2,
                                         float& c3, uint32_t a0, uint32_t a1,
                                         uint32_t a2, uint32_t a3,
                                         uint32_t b0, uint32_t b1) {
    asm volatile(
        "mma.sync.aligned.m16n8k16.row.col.f32.bf16.bf16.f32 "
        "{%0,%1,%2,%3},{%4,%5,%6,%7},{%8,%9},{%0,%1,%2,%3};"
        : "+f"(c0), "+f"(c1), "+f"(c2), "+f"(c3)
        : "r"(a0), "r"(a1), "r"(a2), "r"(a3), "r"(b0), "r"(b1));
}

__global__ void __launch_bounds__(256, 1)
finalize_mma_kernel(const float* __restrict__ x,
                    const float* __restrict__ bias,
                    const float* __restrict__ avg_ptr,
                    float* __restrict__ out,
                    int N) {
    extern __shared__ __nv_bfloat16 Ybuf[];        // Yh [64][456], Yl [64][456]
    __nv_bfloat16* Yh = Ybuf;
    __nv_bfloat16* Yl = Ybuf + TM * YSTRIDE;
    __shared__ float f1s[TM], f2s[TM];

    const int tid = threadIdx.x;
    const int node0 = blockIdx.x * TM;

    // per-node degree factors
    if (tid < TM) {
        int n = node0 + tid;
        float f1 = 0.f, f2 = 0.f;
        if (n < N) {
            float avg = __ldg(avg_ptr);
            float degf = (float)(g_rowptr[n + 1] - g_rowptr[n]);
            float logd = __logf(degf + 1.0f);
            f1 = logd * __frcp_rn(avg);
            f2 = avg * __frcp_rn(logd + EPSV);
        }
        f1s[tid] = f1;
        f2s[tid] = f2;
    }
    __syncthreads();

    // stage Y (factor-folded, 7 segments) as bf16 hi/lo
    #pragma unroll
    for (int t = 0; t < 16; ++t) {
        int p = tid + t * 256;
        int nl = p >> 6;
        int i = p & 63;
        int n = node0 + nl;
        float mean = 0.f, stdv = 0.f, xv = 0.f;
        if (n < N) {
            mean = g_s1[(size_t)n * D + i];
            float s2v = g_s2[(size_t)n * D + i];
            float v = fmaxf(s2v - mean * mean, 0.f) + EPSV;
            stdv = v * rsqrtf(v);
            xv = __ldg(x + (size_t)n * D + i);
        }
        float f1 = f1s[nl], f2 = f2s[nl];
        float seg[7] = { mean, f1 * mean, f2 * mean,
                         stdv, f1 * stdv, f2 * stdv, xv };
        __nv_bfloat16* Yhr = Yh + nl * YSTRIDE + i;
        __nv_bfloat16* Ylr = Yl + nl * YSTRIDE + i;
        #pragma unroll
        for (int sgi = 0; sgi < 7; ++sgi) {
            __nv_bfloat16 h, l;
            bf16_split(seg[sgi], h, l);
            Yhr[sgi * 64] = h;
            Ylr[sgi * 64] = l;
        }
    }
    __syncthreads();

    const int wid = tid >> 5;
    const int lane = tid & 31;
    const int mi = wid & 3;            // node group: mi*16 .. +15
    const int nh = wid >> 2;           // out half: nh*32 .. +31
    const int g = lane >> 2;
    const int tg = lane & 3;

    const int row0 = (mi * 16 + g) * YSTRIDE;      // bf16 offset
    const int row8 = row0 + 8 * YSTRIDE;

    float acc[4][4];
    #pragma unroll
    for (int f = 0; f < 4; ++f)
        #pragma unroll
        for (int q = 0; q < 4; ++q) acc[f][q] = 0.f;

    // 3 passes: (Yh,Wh), (Yh,Wl), (Yl,Wh)
    #pragma unroll
    for (int pass = 0; pass < 3; ++pass) {
        const __nv_bfloat16* Ya = (pass < 2) ? Yh : Yl;
        const unsigned long long* Wb = (pass == 1) ? g_wfl : g_wfh;
        #pragma unroll 4
        for (int s = 0; s < KSTEPS; ++s) {
            int kk = s * 16 + tg * 2;
            uint32_t a0 = *(const uint32_t*)(Ya + row0 + kk);
            uint32_t a1 = *(const uint32_t*)(Ya + row8 + kk);
            uint32_t a2 = *(const uint32_t*)(Ya + row0 + kk + 8);
            uint32_t a3 = *(const uint32_t*)(Ya + row8 + kk + 8);
            #pragma unroll
            for (int f = 0; f < 4; ++f) {
                int fg = nh * 4 + f;
                unsigned long long bv =
                    __ldg(&Wb[(s * 8 + fg) * 32 + lane]);
                mma16816(acc[f][0], acc[f][1], acc[f][2], acc[f][3],
                         a0, a1, a2, a3,
                         (uint32_t)bv, (uint32_t)(bv >> 32));
            }
        }
    }

    // epilogue: +bias, write
    #pragma unroll
    for (int f = 0; f < 4; ++f) {
        int o = nh * 32 + f * 8 + tg * 2;
        float b0 = __ldg(bias + o);
        float b1 = __ldg(bias + o + 1);
        int n0 = node0 + mi * 16 + g;
        int n1 = n0 + 8;
        if (n0 < N) {
            *reinterpret_cast<float2*>(out + (size_t)n0 * D + o) =
                make_float2(acc[f][0] + b0, acc[f][1] + b1);
        }
        if (n1 < N) {
            *reinterpret_cast<float2*>(out + (size_t)n1 * D + o) =
                make_float2(acc[f][2] + b0, acc[f][3] + b1);
        }
    }
}

// ---------------------------------------------------------------------------
// Launch. Inputs: x, edge_row, edge_col, pre_w, lin_w, bias, avg_deg_log
// ---------------------------------------------------------------------------
extern "C" void kernel_launch(void* const* d_in, const int* in_sizes, int n_in,
                              void* d_out, int out_size) {
    const float* x       = (const float*)d_in[0];
    const int*   erow    = (const int*)d_in[1];
    const int*   ecol    = (const int*)d_in[2];
    const float* pre_w   = (const float*)d_in[3];
    const float* lin_w   = (const float*)d_in[4];
    const float* bias    = (const float*)d_in[5];
    const float* avg_log = (const float*)d_in[6];

    const int N = in_sizes[0] / D;
    const int E = in_sizes[1];
    float* out = (float*)d_out;

    permute_zero_kernel<<<(N + 255) / 256, 256>>>(pre_w, lin_w, N);
    count_rank_kernel<<<(E + 255) / 256, 256>>>(erow, E);
    int nsb = (N + SCAN_BLK - 1) / SCAN_BLK;
    scan_block_kernel<<<nsb, SCAN_BLK>>>(N);
    scan_top_kernel<<<1, 128>>>(nsb);
    scan_add_kernel<<<(N + 256) / 256, 256>>>(N, E);
    scatter_kernel<<<(E + 255) / 256, 256>>>(erow, ecol, E);

    {
        long long threads = (long long)N * 16;
        int blocks = (int)((threads + 255) / 256);
        aggregate_kernel<<<blocks, 256>>>(x, N);
    }

    {
        cudaFuncSetAttribute(finalize_mma_kernel,
                             cudaFuncAttributeMaxDynamicSharedMemorySize,
                             FIN_SMEM);
        int blocks = (N + TM - 1) / TM;
        finalize_mma_kernel<<<blocks, 256, FIN_SMEM>>>(
            x, bias, avg_log, out, N);
    }
}